// round 14
// baseline (speedup 1.0000x reference)
#include <cuda_runtime.h>
#include <math.h>

#define N_NODES 50000
#define D 256
#define D4 1024
#define NQ 128
#define PG 256
#define E1C 32768
#define E0C 32768
#define ME 64
#define SPAD 132

// gemm128t smem geometry (float2 units): X 2 stages x 8 k x 132 rows, W 2 x 8 x 260
#define XS_STRIDE 132
#define WS_STRIDE 260
#define XS_STAGE (8 * XS_STRIDE)
#define WS_STAGE (8 * WS_STRIDE)
#define XS_TOTAL (2 * XS_STAGE)
#define SMEMB ((XS_TOTAL + 2 * WS_STAGE) * 8)

// ---------------- scratch (static device globals; referenced ONLY from device code) ----------------
__device__ __align__(16) float g_M[D4 * D4];   // Wq^T Wk
__device__ __align__(16) float g_v[NQ * D];
__device__ __align__(16) float g_wz[NQ * D];
__device__ __align__(16) float g_u[NQ * D];
__device__ float g_c[NQ];
__device__ __align__(16) float g_T1[N_NODES * D];
__device__ __align__(16) float g_T2[N_NODES * D];
__device__ __align__(16) float g_R1[E1C * D];
__device__ __align__(16) float g_R2[E1C * D];
__device__ float g_logits[E1C];
__device__ float g_exp[E1C];
__device__ float g_soft[E1C];
__device__ float g_target[E1C];
__device__ unsigned g_segmax[N_NODES];
__device__ float g_segsum[N_NODES];
__device__ int g_flag[N_NODES];
__device__ __align__(16) float g_NR1[N_NODES * D];
__device__ __align__(16) float g_NR2[N_NODES * D];
__device__ int g_s1[E1C], g_d1[E1C], g_q1[E1C];
__device__ int g_s0[E0C], g_d0[E0C], g_q0[E0C];
__device__ int g_psrc[NQ * ME], g_pdst[NQ * ME];
__device__ float g_psoft[NQ * ME], g_ptgt[NQ * ME];

// compaction of dst-node sets (tables only needed at dst rows)
__device__ int g_need1[N_NODES], g_need0[N_NODES];
__device__ int g_cid1[N_NODES], g_cid0[N_NODES];
__device__ int g_nl1[N_NODES], g_nl0[N_NODES];
__device__ int g_cnt1, g_cnt0;

// pre-split W operands: packed float2(hi,lo) per element, row-major [row][k]
__device__ __align__(16) float2 g_sWT[512 * D];
__device__ __align__(16) float2 g_sWR[512 * D];
__device__ __align__(16) float2 g_sWL[256 * D];

#define BUF_T1 1
#define BUF_T2 2
#define BUF_R1 3
#define BUF_R2 4
#define BUF_NR1 5
#define BUF_NR2 6

__device__ __forceinline__ float* dbuf(int id) {
    switch (id) {
        case BUF_T1: return g_T1;
        case BUF_T2: return g_T2;
        case BUF_R1: return g_R1;
        case BUF_R2: return g_R2;
        case BUF_NR1: return g_NR1;
        default: return g_NR2;
    }
}

__device__ __forceinline__ unsigned fenc(float f) {
    unsigned u = __float_as_uint(f);
    return (u & 0x80000000u) ? ~u : (u | 0x80000000u);
}
__device__ __forceinline__ float fdec(unsigned e) {
    return __uint_as_float((e & 0x80000000u) ? (e ^ 0x80000000u) : ~e);
}

__device__ __forceinline__ unsigned f2tf32(float x) {
    unsigned r;
    asm("cvt.rna.tf32.f32 %0, %1;" : "=r"(r) : "f"(x));
    return r;
}

__device__ __forceinline__ void mma_tf32(float* c, unsigned a0, unsigned a1, unsigned a2,
                                         unsigned a3, unsigned b0, unsigned b1) {
    asm volatile(
        "mma.sync.aligned.m16n8k8.row.col.f32.tf32.tf32.f32 "
        "{%0,%1,%2,%3}, {%4,%5,%6,%7}, {%8,%9}, {%0,%1,%2,%3};"
        : "+f"(c[0]), "+f"(c[1]), "+f"(c[2]), "+f"(c[3])
        : "r"(a0), "r"(a1), "r"(a2), "r"(a3), "r"(b0), "r"(b1));
}

__device__ __forceinline__ float2 splitpack(float v) {
    unsigned h = f2tf32(v);
    unsigned l = f2tf32(v - __uint_as_float(h));
    return make_float2(__uint_as_float(h), __uint_as_float(l));
}

// ---------------- tensor-core split-tf32 GEMM ----------------
// C[R x 256-per-yblock] = act( X @ W^T + bias ). W pre-split (wsel: 1=WT, 2=WR, 3=WL).
// Optional row gather (gsel: 1=(nl1,cnt1), 2=(nl0,cnt0)).
// Block tile 128x256, 8 warps in 2(m) x 4(n) of 64x64 warp tiles.
// K_BLK=8 double-buffered pipeline, one barrier per chunk. Dynamic smem (SMEMB).
// blockIdx.y selects output: 0 -> c1 (W rows [0,256)), 1 -> c2 (W rows [256,512)).
__global__ __launch_bounds__(256) void k_gemm128t(
    const float* __restrict__ xext, int xid, int R,
    int wsel,
    const float* __restrict__ bias, int act,
    float* __restrict__ c1ext, int c1id, int c2id,
    int gsel)
{
    extern __shared__ __align__(16) float2 sm[];
    const float* X = xid ? dbuf(xid) : xext;
    const float2* sW = (wsel == 1) ? g_sWT : (wsel == 2) ? g_sWR : g_sWL;
    const int* gather = (gsel == 1) ? g_nl1 : (gsel == 2) ? g_nl0 : nullptr;

    int Reff = R;
    if (gsel == 1) Reff = g_cnt1;
    else if (gsel == 2) Reff = g_cnt0;

    const int r0 = blockIdx.x * 128;
    if (r0 >= Reff) return;
    const int j0w = blockIdx.y * 256;   // W row base

    float* Cbase;
    if (c1id == 0 && c2id == 0) Cbase = c1ext;
    else Cbase = blockIdx.y ? dbuf(c2id) : dbuf(c1id);

    const int tid = threadIdx.x;
    const int wid = tid >> 5;
    const int lane = tid & 31;
    const int m0 = (wid >> 2) * 64;
    const int n0 = (wid & 3) * 64;
    const int g = lane >> 2;
    const int t4 = lane & 3;

#define XS(st, k, r) sm[(st) * XS_STAGE + (k) * XS_STRIDE + (r)]
#define WS(st, k, r) sm[XS_TOTAL + (st) * WS_STAGE + (k) * WS_STRIDE + (r)]

    // G2S mapping
    const int xrow = tid >> 1;              // 0..127
    const int xkq = (tid & 1) << 2;         // 0 or 4
    const int lrow = r0 + xrow;
    const bool xok = lrow < Reff;
    int grow = lrow;
    if (gather && xok) grow = gather[lrow];
    const float* Xrow = X + (size_t)grow * D + xkq;
    const int wrow0 = tid >> 1;             // assignment 0: rows 0..127
    const int wrow1 = (tid + 256) >> 1;     // assignment 1: rows 128..255
    const int wkq = (tid & 1) << 2;
    const float2* Wp0 = sW + (size_t)(j0w + wrow0) * D + wkq;
    const float2* Wp1 = sW + (size_t)(j0w + wrow1) * D + wkq;

    float c[4][8][4];
#pragma unroll
    for (int mi = 0; mi < 4; mi++)
#pragma unroll
        for (int nj = 0; nj < 8; nj++)
#pragma unroll
            for (int k = 0; k < 4; k++) c[mi][nj][k] = 0.f;

    float4 xv = make_float4(0.f, 0.f, 0.f, 0.f);
    float4 w0a, w0b, w1a, w1b;

    // prime chunk 0
    if (xok) xv = *(const float4*)(Xrow);
    w0a = ((const float4*)Wp0)[0]; w0b = ((const float4*)Wp0)[1];
    w1a = ((const float4*)Wp1)[0]; w1b = ((const float4*)Wp1)[1];
    XS(0, xkq + 0, xrow) = splitpack(xv.x); XS(0, xkq + 1, xrow) = splitpack(xv.y);
    XS(0, xkq + 2, xrow) = splitpack(xv.z); XS(0, xkq + 3, xrow) = splitpack(xv.w);
    WS(0, wkq + 0, wrow0) = make_float2(w0a.x, w0a.y);
    WS(0, wkq + 1, wrow0) = make_float2(w0a.z, w0a.w);
    WS(0, wkq + 2, wrow0) = make_float2(w0b.x, w0b.y);
    WS(0, wkq + 3, wrow0) = make_float2(w0b.z, w0b.w);
    WS(0, wkq + 0, wrow1) = make_float2(w1a.x, w1a.y);
    WS(0, wkq + 1, wrow1) = make_float2(w1a.z, w1a.w);
    WS(0, wkq + 2, wrow1) = make_float2(w1b.x, w1b.y);
    WS(0, wkq + 3, wrow1) = make_float2(w1b.z, w1b.w);
    __syncthreads();

    for (int kb = 0; kb < 32; kb++) {
        const int cur = kb & 1, nxt = cur ^ 1;
        if (kb < 31) {
            int k0 = (kb + 1) * 8;
            xv = make_float4(0.f, 0.f, 0.f, 0.f);
            if (xok) xv = *(const float4*)(Xrow + k0);
            w0a = ((const float4*)(Wp0 + k0))[0]; w0b = ((const float4*)(Wp0 + k0))[1];
            w1a = ((const float4*)(Wp1 + k0))[0]; w1b = ((const float4*)(Wp1 + k0))[1];
        }
        {
            float2 b0[8], b1[8];
#pragma unroll
            for (int nj = 0; nj < 8; nj++) {
                int nc = n0 + nj * 8 + g;
                b0[nj] = WS(cur, t4, nc);
                b1[nj] = WS(cur, 4 + t4, nc);
            }
#pragma unroll
            for (int mi = 0; mi < 4; mi++) {
                int mr = m0 + mi * 16;
                float2 a0 = XS(cur, t4, mr + g);
                float2 a1 = XS(cur, t4, mr + 8 + g);
                float2 a2 = XS(cur, 4 + t4, mr + g);
                float2 a3 = XS(cur, 4 + t4, mr + 8 + g);
                unsigned ah0 = __float_as_uint(a0.x), al0 = __float_as_uint(a0.y);
                unsigned ah1 = __float_as_uint(a1.x), al1 = __float_as_uint(a1.y);
                unsigned ah2 = __float_as_uint(a2.x), al2 = __float_as_uint(a2.y);
                unsigned ah3 = __float_as_uint(a3.x), al3 = __float_as_uint(a3.y);
#pragma unroll
                for (int nj = 0; nj < 8; nj++) {
                    unsigned bh0 = __float_as_uint(b0[nj].x), bl0 = __float_as_uint(b0[nj].y);
                    unsigned bh1 = __float_as_uint(b1[nj].x), bl1 = __float_as_uint(b1[nj].y);
                    mma_tf32(c[mi][nj], al0, al1, al2, al3, bh0, bh1);
                    mma_tf32(c[mi][nj], ah0, ah1, ah2, ah3, bl0, bl1);
                    mma_tf32(c[mi][nj], ah0, ah1, ah2, ah3, bh0, bh1);
                }
            }
        }
        if (kb < 31) {
            XS(nxt, xkq + 0, xrow) = splitpack(xv.x); XS(nxt, xkq + 1, xrow) = splitpack(xv.y);
            XS(nxt, xkq + 2, xrow) = splitpack(xv.z); XS(nxt, xkq + 3, xrow) = splitpack(xv.w);
            WS(nxt, wkq + 0, wrow0) = make_float2(w0a.x, w0a.y);
            WS(nxt, wkq + 1, wrow0) = make_float2(w0a.z, w0a.w);
            WS(nxt, wkq + 2, wrow0) = make_float2(w0b.x, w0b.y);
            WS(nxt, wkq + 3, wrow0) = make_float2(w0b.z, w0b.w);
            WS(nxt, wkq + 0, wrow1) = make_float2(w1a.x, w1a.y);
            WS(nxt, wkq + 1, wrow1) = make_float2(w1a.z, w1a.w);
            WS(nxt, wkq + 2, wrow1) = make_float2(w1b.x, w1b.y);
            WS(nxt, wkq + 3, wrow1) = make_float2(w1b.z, w1b.w);
        }
        __syncthreads();
    }

    // epilogue: frag (mi,nj): rows m0+mi*16+half*8+g, cols n0+nj*8+t4*2
#pragma unroll
    for (int mi = 0; mi < 4; mi++) {
#pragma unroll
        for (int half = 0; half < 2; half++) {
            int orow = r0 + m0 + mi * 16 + half * 8 + g;
            if (orow < Reff) {
#pragma unroll
                for (int nj = 0; nj < 8; nj++) {
                    int col = n0 + nj * 8 + t4 * 2;
                    float v0 = c[mi][nj][half * 2 + 0];
                    float v1 = c[mi][nj][half * 2 + 1];
                    if (bias) { v0 += bias[col]; v1 += bias[col + 1]; }
                    if (act) {
                        v0 = v0 > 0.f ? v0 : 0.01f * v0;
                        v1 = v1 > 0.f ? v1 : 0.01f * v1;
                    }
                    *(float2*)(Cbase + (size_t)orow * D + col) = make_float2(v0, v1);
                }
            }
        }
    }
#undef XS
#undef WS
}

// g_M = A^T * B (A, B 1024x1024 row-major), fp32 SIMT (small share of total)
__global__ __launch_bounds__(256) void k_gemm128_tn(const float* __restrict__ A,
                                                    const float* __restrict__ B) {
    __shared__ float As[2][16][SPAD];
    __shared__ float Bs[2][16][SPAD];

    const int i0 = blockIdx.x * 128;
    const int j0 = blockIdx.y * 128;
    const int tid = threadIdx.x;
    const int tx = tid & 15, ty = tid >> 4;

    float acc[8][8];
#pragma unroll
    for (int r = 0; r < 8; r++)
#pragma unroll
        for (int c = 0; c < 8; c++) acc[r][c] = 0.f;

    float4 xs[2], ws[2];

#pragma unroll
    for (int i = 0; i < 2; i++) {
        int f = tid + i * 256;
        int i4 = (f & 31) << 2, kk = f >> 5;
        *(float4*)&As[0][kk][i4] = *(const float4*)(A + (size_t)kk * D4 + i0 + i4);
        *(float4*)&Bs[0][kk][i4] = *(const float4*)(B + (size_t)kk * D4 + j0 + i4);
    }
    __syncthreads();

    for (int kb = 0; kb < 64; kb++) {
        int cur = kb & 1, nxt = cur ^ 1;
        if (kb < 63) {
            int k0 = (kb + 1) * 16;
#pragma unroll
            for (int i = 0; i < 2; i++) {
                int f = tid + i * 256;
                int i4 = (f & 31) << 2, kk = f >> 5;
                xs[i] = *(const float4*)(A + (size_t)(k0 + kk) * D4 + i0 + i4);
                ws[i] = *(const float4*)(B + (size_t)(k0 + kk) * D4 + j0 + i4);
            }
        }
#pragma unroll
        for (int kk = 0; kk < 16; kk++) {
            float a[8], b[8];
            *(float4*)&a[0] = *(const float4*)&As[cur][kk][ty * 8];
            *(float4*)&a[4] = *(const float4*)&As[cur][kk][ty * 8 + 4];
            *(float4*)&b[0] = *(const float4*)&Bs[cur][kk][tx * 8];
            *(float4*)&b[4] = *(const float4*)&Bs[cur][kk][tx * 8 + 4];
#pragma unroll
            for (int r = 0; r < 8; r++)
#pragma unroll
                for (int c = 0; c < 8; c++) acc[r][c] += a[r] * b[c];
        }
        if (kb < 63) {
#pragma unroll
            for (int i = 0; i < 2; i++) {
                int f = tid + i * 256;
                int i4 = (f & 31) << 2, kk = f >> 5;
                *(float4*)&As[nxt][kk][i4] = xs[i];
                *(float4*)&Bs[nxt][kk][i4] = ws[i];
            }
            __syncthreads();
        }
    }

#pragma unroll
    for (int r = 0; r < 8; r++) {
        float* crow = g_M + (size_t)(i0 + ty * 8 + r) * D4 + j0 + tx * 8;
        *(float4*)crow = *(float4*)&acc[r][0];
        *(float4*)(crow + 4) = *(float4*)&acc[r][4];
    }
}

// pre-split W into packed float2(hi,lo). mode 1: WT from g_M[.][0:256];
// mode 2: WR from g_M[.][256:512]; mode 3: WL from ext (256x256 row-major).
__global__ void k_splitw(const float* __restrict__ ext, int mode) {
    int i = blockIdx.x * blockDim.x + threadIdx.x;
    int total = (mode == 3 ? 256 : 512) * D;
    if (i >= total) return;
    int r = i >> 8, cidx = i & 255;
    float v;
    if (mode == 1) v = g_M[(size_t)r * D4 + cidx];
    else if (mode == 2) v = g_M[(size_t)r * D4 + 256 + cidx];
    else v = ext[i];
    float2 p = splitpack(v);
    if (mode == 1) g_sWT[i] = p;
    else if (mode == 2) g_sWR[i] = p;
    else g_sWL[i] = p;
}

// edges are int32 rows of stride s32 (8 for int32 data, 16 for int64-as-int32; field f at f*fm)
__global__ void k_extract(const int* __restrict__ e1, const int* __restrict__ e0,
                          int s32, int fm) {
    int i = blockIdx.x * blockDim.x + threadIdx.x;
    if (i < E1C) {
        int q = e1[(size_t)i * s32 + 0 * fm];
        int s = e1[(size_t)i * s32 + 6 * fm];
        int d = e1[(size_t)i * s32 + 7 * fm];
        g_q1[i] = ((unsigned)q < NQ) ? q : 0;
        g_s1[i] = ((unsigned)s < N_NODES) ? s : 0;
        g_d1[i] = ((unsigned)d < N_NODES) ? d : 0;
    }
    if (i < E0C) {
        int q = e0[(size_t)i * s32 + 0 * fm];
        int s = e0[(size_t)i * s32 + 6 * fm];
        int d = e0[(size_t)i * s32 + 7 * fm];
        g_q0[i] = ((unsigned)q < NQ) ? q : 0;
        g_s0[i] = ((unsigned)s < N_NODES) ? s : 0;
        g_d0[i] = ((unsigned)d < N_NODES) ? d : 0;
    }
}

// dst-set compaction
__global__ void k_markinit() {
    int i = blockIdx.x * blockDim.x + threadIdx.x;
    if (i < N_NODES) { g_need1[i] = 0; g_need0[i] = 0; }
    if (i == 0) { g_cnt1 = 0; g_cnt0 = 0; }
}
__global__ void k_mark() {
    int i = blockIdx.x * blockDim.x + threadIdx.x;
    if (i < E1C) g_need1[g_d1[i]] = 1;
    if (i < E0C) g_need0[g_d0[i]] = 1;
}
__global__ void k_compact() {
    int i = blockIdx.x * blockDim.x + threadIdx.x;
    if (i < N_NODES) {
        if (g_need1[i]) { int p = atomicAdd(&g_cnt1, 1); g_cid1[i] = p; g_nl1[p] = i; }
        if (g_need0[i]) { int p = atomicAdd(&g_cnt0, 1); g_cid0[i] = p; g_nl0[p] = i; }
    }
}

// per-query vectors from blocks of M = Wq^T Wk
__global__ void k_queryvec(const float* __restrict__ qst, const float* __restrict__ qr) {
    int q = blockIdx.x;
    int j = threadIdx.x;
    __shared__ float ss[256], tt[256], red[256];
    ss[j] = qst[q * D + j];
    tt[j] = qr[q * D + j];
    __syncthreads();
    int which = blockIdx.y;
    if (which == 0) {
        const float* row = g_M + (size_t)j * D4;
        float a = 0.f;
        for (int k = 0; k < D; k++) a += row[512 + k] * ss[k] + row[768 + k] * tt[k];
        g_v[q * D + j] = a;
    } else if (which == 1) {
        const float* row = g_M + (size_t)(256 + j) * D4;
        float a = 0.f;
        for (int k = 0; k < D; k++) a += row[512 + k] * ss[k] + row[768 + k] * tt[k];
        for (int k = 0; k < D; k++)
            a += g_M[(size_t)(512 + k) * D4 + 256 + j] * ss[k]
               + g_M[(size_t)(768 + k) * D4 + 256 + j] * tt[k];
        g_wz[q * D + j] = a;
    } else if (which == 2) {
        float a = 0.f;
        for (int k = 0; k < D; k++)
            a += g_M[(size_t)(512 + k) * D4 + j] * ss[k]
               + g_M[(size_t)(768 + k) * D4 + j] * tt[k];
        g_u[q * D + j] = a;
    } else {
        const float* rs = g_M + (size_t)(512 + j) * D4;
        const float* rt = g_M + (size_t)(768 + j) * D4;
        float ps = 0.f, pt = 0.f;
        for (int k = 0; k < D; k++) {
            ps += rs[512 + k] * ss[k] + rs[768 + k] * tt[k];
            pt += rt[512 + k] * ss[k] + rt[768 + k] * tt[k];
        }
        red[j] = ss[j] * ps + tt[j] * pt;
        __syncthreads();
        for (int s = 128; s; s >>= 1) {
            if (j < s) red[j] += red[j + s];
            __syncthreads();
        }
        if (j == 0) g_c[q] = red[0];
    }
}

// one warp per edge; T tables indexed through the pass's compact id map
__global__ void k_edge_score(int pass, int nrid, const float* __restrict__ nrext,
                             const float* __restrict__ rel, int ne) {
    int e = blockIdx.x * 8 + (threadIdx.x >> 5);
    if (e >= ne) return;
    int lane = threadIdx.x & 31;
    const int* qs = pass ? g_q1 : g_q0;
    const int* ssrc = pass ? g_s1 : g_s0;
    const int* sdst = pass ? g_d1 : g_d0;
    const int* cid = pass ? g_cid1 : g_cid0;
    const float* NR = nrid ? dbuf(nrid) : nrext;
    int q = qs[e], s = ssrc[e], d = sdst[e];
    int cd = cid[d];
    const float* ns = NR + (size_t)s * D;
    const float* nd = NR + (size_t)d * D;
    const float* re = rel + (size_t)e * D;
    const float* t1 = g_T1 + (size_t)cd * D;
    const float* t2 = g_T2 + (size_t)cd * D;
    const float* r1 = g_R1 + (size_t)e * D;
    const float* r2 = g_R2 + (size_t)e * D;
    const float* vq = g_v + q * D;
    const float* wq = g_wz + q * D;
    const float* uq = g_u + q * D;
    float a = 0.f;
#pragma unroll
    for (int i = 0; i < 8; i++) {
        int k = lane + 32 * i;
        a += ns[k] * (t1[k] + r1[k] + vq[k]);
        a += re[k] * (t2[k] + r2[k] + wq[k]);
        a += uq[k] * nd[k];
    }
#pragma unroll
    for (int o = 16; o; o >>= 1) a += __shfl_xor_sync(0xffffffffu, a, o);
    if (lane == 0) g_logits[e] = a + g_c[q];
}

__global__ void k_seg_init() {
    int i = blockIdx.x * blockDim.x + threadIdx.x;
    if (i < N_NODES) {
        g_segmax[i] = 0u;
        g_segsum[i] = 0.f;
        g_flag[i] = 0;
    }
}

__global__ void k_seg_max(int pass, int ne) {
    int i = blockIdx.x * blockDim.x + threadIdx.x;
    if (i < ne) {
        const int* seg = pass ? g_s1 : g_s0;
        atomicMax(&g_segmax[seg[i]], fenc(g_logits[i]));
    }
}

__global__ void k_seg_exp(int pass, int ne) {
    int i = blockIdx.x * blockDim.x + threadIdx.x;
    if (i < ne) {
        const int* seg = pass ? g_s1 : g_s0;
        float m = fdec(g_segmax[seg[i]]);
        float e = expf(g_logits[i] - m);
        g_exp[i] = e;
        atomicAdd(&g_segsum[seg[i]], e);
    }
}

__global__ void k_seg_div(int pass, const float* __restrict__ vscore, int ne) {
    int i = blockIdx.x * blockDim.x + threadIdx.x;
    if (i < ne) {
        const int* seg = pass ? g_s1 : g_s0;
        float sft = g_exp[i] / g_segsum[seg[i]];
        g_soft[i] = sft;
        if (vscore) g_target[i] = sft * vscore[seg[i]];
    }
}

// per-query bitonic sort of 256 (target, idx), descending value, ties by ascending idx
__global__ void k_topk(const int* __restrict__ edges1, int s32, int fm,
                       float* __restrict__ out_pe, float* __restrict__ out_oi) {
    int q = blockIdx.x;
    int t = threadIdx.x;
    __shared__ float sv[256];
    __shared__ int si[256];
    sv[t] = g_target[q * PG + t];
    si[t] = t;
    __syncthreads();
    for (int k = 2; k <= 256; k <<= 1) {
        for (int j = k >> 1; j > 0; j >>= 1) {
            int ixj = t ^ j;
            if (ixj > t) {
                float va = sv[t], vb = sv[ixj];
                int ia = si[t], ib = si[ixj];
                bool before = (va > vb) || (va == vb && ia < ib);
                bool up = ((t & k) == 0);
                if (up ? !before : before) {
                    sv[t] = vb; sv[ixj] = va;
                    si[t] = ib; si[ixj] = ia;
                }
            }
            __syncthreads();
        }
    }
    if (t < ME) {
        int oi = q * PG + si[t];
        int po = q * ME + t;
        out_oi[po] = (float)oi;
#pragma unroll
        for (int f = 0; f < 8; f++)
            out_pe[(size_t)po * 8 + f] = (float)edges1[(size_t)oi * s32 + f * fm];
        int s = edges1[(size_t)oi * s32 + 6 * fm];
        int d = edges1[(size_t)oi * s32 + 7 * fm];
        g_psrc[po] = ((unsigned)s < N_NODES) ? s : 0;
        g_pdst[po] = ((unsigned)d < N_NODES) ? d : 0;
        g_psoft[po] = g_soft[oi];
        g_ptgt[po] = sv[t];
    }
}

__global__ void k_zero_score(float* __restrict__ out_score) {
    int i = blockIdx.x * blockDim.x + threadIdx.x;
    if (i < N_NODES) out_score[i] = 0.f;
}

__global__ void k_scatter_score_flag(float* __restrict__ out_score) {
    int i = blockIdx.x * blockDim.x + threadIdx.x;
    if (i < NQ * ME) {
        atomicAdd(&out_score[g_pdst[i]], g_ptgt[i]);
        g_flag[g_psrc[i]] = 1;
    }
}

__global__ void k_set_flag0() {
    int i = blockIdx.x * blockDim.x + threadIdx.x;
    if (i < E0C) g_flag[g_s0[i]] = 1;
}

// mode 0: out = g_NR1, in = external NR ; mode 1: out = g_NR2, in = g_NR1
__global__ void k_scale_repr(int mode, const float* __restrict__ nrext) {
    size_t i = (size_t)blockIdx.x * blockDim.x + threadIdx.x;
    if (i < (size_t)N_NODES * (D / 4)) {
        const float4* in = mode ? (const float4*)g_NR1 : (const float4*)nrext;
        float4* out = mode ? (float4*)g_NR2 : (float4*)g_NR1;
        int n = (int)(i >> 6);
        float sc = g_flag[n] ? 0.2f : 1.0f;
        float4 vv = in[i];
        vv.x *= sc; vv.y *= sc; vv.z *= sc; vv.w *= sc;
        out[i] = vv;
    }
}

// mode 0: pruned edges, base external NR, acc g_NR1 ; mode 1: edges0, base g_NR1, acc g_NR2
__global__ void k_edge_agg(int mode, const float* __restrict__ nrext, int ne) {
    int e = blockIdx.x * 8 + (threadIdx.x >> 5);
    if (e >= ne) return;
    int lane = threadIdx.x & 31;
    const int* src = mode ? g_s0 : g_psrc;
    const int* dst = mode ? g_d0 : g_pdst;
    const float* w = mode ? g_soft : g_psoft;
    const float* base = mode ? g_NR1 : nrext;
    float* acc = mode ? g_NR2 : g_NR1;
    float cf = 0.8f * w[e];
    const float* bd = base + (size_t)dst[e] * D;
    float* as = acc + (size_t)src[e] * D;
#pragma unroll
    for (int i = 0; i < 8; i++) atomicAdd(as + lane + 32 * i, cf * bd[lane + 32 * i]);
}

// ---------------- host: kernel launches ONLY ----------------
extern "C" void kernel_launch(void* const* d_in, const int* in_sizes, int n_in,
                              void* d_out, int out_size) {
    int iVS = -1, iNR = -1, iE0 = -1, iE1 = -1, iR0 = -1, iR1 = -1;
    int iQA = -1, iQB = -1, iWA = -1, iWB = -1, iWL = -1, iBL = -1;
    for (int i = 0; i < n_in; i++) {
        long sz = in_sizes[i];
        if (sz == 50000) iVS = i;
        else if (sz == 12800000) iNR = i;
        else if (sz == 262144 || sz == 524288) { if (iE0 < 0) iE0 = i; else iE1 = i; }
        else if (sz == 8388608) { if (iR0 < 0) iR0 = i; else iR1 = i; }
        else if (sz == 32768) { if (iQA < 0) iQA = i; else iQB = i; }
        else if (sz == 1048576) { if (iWA < 0) iWA = i; else iWB = i; }
        else if (sz == 65536) iWL = i;
        else if (sz == 256) iBL = i;
    }
    bool dictOrder = (in_sizes[0] == 50000);

    const float* vscore = (const float*)d_in[iVS];
    const float* NR = (const float*)d_in[iNR];
    const int* e0 = (const int*)d_in[iE0];
    const int* e1 = (const int*)d_in[iE1];
    const float* rel0 = (const float*)d_in[iR0];
    const float* rel1 = (const float*)d_in[iR1];
    const float* qst = (const float*)d_in[dictOrder ? iQA : iQB];
    const float* qr = (const float*)d_in[dictOrder ? iQB : iQA];
    const float* Wq = (const float*)d_in[dictOrder ? iWA : iWB];
    const float* Wk = (const float*)d_in[dictOrder ? iWB : iWA];
    const float* Wl = (const float*)d_in[iWL];
    const float* bl = (const float*)d_in[iBL];

    int s32 = in_sizes[iE0] / 32768;
    int fm = s32 >> 3;

    float* out = (float*)d_out;
    float* out_score = out;
    float* out_repr = out + N_NODES;
    float* out_pe = out_repr + (size_t)N_NODES * D;
    float* out_oi = out_pe + (size_t)NQ * ME * 8;

    const int NB50K = (N_NODES + 255) / 256;
    const int GRN = (N_NODES + 127) / 128;   // 391
    const int GRE = E1C / 128;               // 256

    // opt-in >48KB dynamic smem for the tensor GEMM (attribute set, not an allocation)
    cudaFuncSetAttribute(k_gemm128t, cudaFuncAttributeMaxDynamicSharedMemorySize, SMEMB);

    k_extract<<<128, 256>>>(e1, e0, s32, fm);
    k_markinit<<<NB50K, 256>>>();
    k_mark<<<128, 256>>>();
    k_compact<<<NB50K, 256>>>();
    k_gemm128_tn<<<dim3(8, 8), 256>>>(Wq, Wk);
    k_splitw<<<512, 256>>>(nullptr, 1);
    k_splitw<<<512, 256>>>(nullptr, 2);
    k_splitw<<<256, 256>>>(Wl, 3);
    k_queryvec<<<dim3(NQ, 4), 256>>>(qst, qr);

    // ---- pass 1 tables: T (compacted dst1 rows) and R (all edges), split-tf32 ----
    k_gemm128t<<<dim3(GRN, 2), 256, SMEMB>>>(NR, 0, N_NODES, 1, nullptr, 0, nullptr, BUF_T1, BUF_T2, 1);
    k_gemm128t<<<dim3(GRE, 2), 256, SMEMB>>>(rel1, 0, E1C, 2, nullptr, 0, nullptr, BUF_R1, BUF_R2, 0);

    // ---- pass 1 scores + segment softmax ----
    k_seg_init<<<NB50K, 256>>>();
    k_edge_score<<<E1C / 8, 256>>>(1, 0, NR, rel1, E1C);
    k_seg_max<<<128, 256>>>(1, E1C);
    k_seg_exp<<<128, 256>>>(1, E1C);
    k_seg_div<<<128, 256>>>(1, vscore, E1C);

    // ---- top-64 per query ----
    k_topk<<<NQ, 256>>>(e1, s32, fm, out_pe, out_oi);

    // ---- updated node score + repr update 1 ----
    k_zero_score<<<NB50K, 256>>>(out_score);
    k_scatter_score_flag<<<(NQ * ME + 255) / 256, 256>>>(out_score);
    k_scale_repr<<<(N_NODES * (D / 4) + 255) / 256, 256>>>(0, NR);
    k_edge_agg<<<NQ * ME / 8, 256>>>(0, NR, NQ * ME);

    // ---- pass 2 tables (compacted dst0 rows) ----
    k_gemm128t<<<dim3(GRN, 2), 256, SMEMB>>>(nullptr, BUF_NR1, N_NODES, 1, nullptr, 0, nullptr, BUF_T1, BUF_T2, 2);
    k_gemm128t<<<dim3(GRE, 2), 256, SMEMB>>>(rel0, 0, E0C, 2, nullptr, 0, nullptr, BUF_R1, BUF_R2, 0);

    // ---- pass 2 scores + softmax ----
    k_seg_init<<<NB50K, 256>>>();
    k_edge_score<<<E0C / 8, 256>>>(0, BUF_NR1, nullptr, rel0, E0C);
    k_seg_max<<<128, 256>>>(0, E0C);
    k_seg_exp<<<128, 256>>>(0, E0C);
    k_seg_div<<<128, 256>>>(0, nullptr, E0C);

    // ---- repr update 2 ----
    k_set_flag0<<<128, 256>>>();
    k_scale_repr<<<(N_NODES * (D / 4) + 255) / 256, 256>>>(1, nullptr);
    k_edge_agg<<<E0C / 8, 256>>>(1, nullptr, E0C);

    // ---- final linear layer + leaky relu (N=256 external out, full node set) ----
    k_gemm128t<<<dim3(GRN, 1), 256, SMEMB>>>(nullptr, BUF_NR2, N_NODES, 3, bl, 1, out_repr, 0, 0, 0);
}

// round 15
// speedup vs baseline: 1.0966x; 1.0966x over previous
#include <cuda_runtime.h>
#include <math.h>

#define N_NODES 50000
#define D 256
#define D4 1024
#define NQ 128
#define PG 256
#define E1C 32768
#define E0C 32768
#define ME 64
#define SPAD 132
#define SP2 132

// ---------------- scratch (static device globals; referenced ONLY from device code) ----------------
__device__ __align__(16) float g_M[D4 * D4];   // Wq^T Wk
__device__ __align__(16) float g_v[NQ * D];
__device__ __align__(16) float g_wz[NQ * D];
__device__ __align__(16) float g_u[NQ * D];
__device__ float g_c[NQ];
__device__ __align__(16) float g_T1[N_NODES * D];
__device__ __align__(16) float g_T2[N_NODES * D];
__device__ __align__(16) float g_R1[E1C * D];
__device__ __align__(16) float g_R2[E1C * D];
__device__ float g_logits[E1C];
__device__ float g_exp[E1C];
__device__ unsigned g_segmax[N_NODES];
__device__ float g_segsum[N_NODES];
__device__ int g_flag[N_NODES];
__device__ __align__(16) float g_NR1[N_NODES * D];
__device__ __align__(16) float g_NR2[N_NODES * D];
__device__ int g_s1[E1C], g_d1[E1C], g_q1[E1C];
__device__ int g_s0[E0C], g_d0[E0C], g_q0[E0C];
__device__ int g_psrc[NQ * ME], g_pdst[NQ * ME];
__device__ float g_psoft[NQ * ME], g_ptgt[NQ * ME];

// compaction of dst-node sets (tables only needed at dst rows)
__device__ int g_need1[N_NODES], g_need0[N_NODES];
__device__ int g_cid1[N_NODES], g_cid0[N_NODES];
__device__ int g_nl1[N_NODES], g_nl0[N_NODES];
__device__ int g_cnt1, g_cnt0;

// pre-split W operands: packed float2(hi,lo) per element, row-major [row][k]
__device__ __align__(16) float2 g_sWT[512 * D];
__device__ __align__(16) float2 g_sWR[512 * D];
__device__ __align__(16) float2 g_sWL[256 * D];

#define BUF_T1 1
#define BUF_T2 2
#define BUF_R1 3
#define BUF_R2 4
#define BUF_NR1 5
#define BUF_NR2 6

__device__ __forceinline__ float* dbuf(int id) {
    switch (id) {
        case BUF_T1: return g_T1;
        case BUF_T2: return g_T2;
        case BUF_R1: return g_R1;
        case BUF_R2: return g_R2;
        case BUF_NR1: return g_NR1;
        default: return g_NR2;
    }
}

__device__ __forceinline__ unsigned fenc(float f) {
    unsigned u = __float_as_uint(f);
    return (u & 0x80000000u) ? ~u : (u | 0x80000000u);
}
__device__ __forceinline__ float fdec(unsigned e) {
    return __uint_as_float((e & 0x80000000u) ? (e ^ 0x80000000u) : ~e);
}

__device__ __forceinline__ unsigned f2tf32(float x) {
    unsigned r;
    asm("cvt.rna.tf32.f32 %0, %1;" : "=r"(r) : "f"(x));
    return r;
}

__device__ __forceinline__ void mma_tf32(float* c, unsigned a0, unsigned a1, unsigned a2,
                                         unsigned a3, unsigned b0, unsigned b1) {
    asm volatile(
        "mma.sync.aligned.m16n8k8.row.col.f32.tf32.tf32.f32 "
        "{%0,%1,%2,%3}, {%4,%5,%6,%7}, {%8,%9}, {%0,%1,%2,%3};"
        : "+f"(c[0]), "+f"(c[1]), "+f"(c[2]), "+f"(c[3])
        : "r"(a0), "r"(a1), "r"(a2), "r"(a3), "r"(b0), "r"(b1));
}

__device__ __forceinline__ float2 splitpack(float v) {
    unsigned h = f2tf32(v);
    unsigned l = f2tf32(v - __uint_as_float(h));
    return make_float2(__uint_as_float(h), __uint_as_float(l));
}

// ---------------- tensor-core split-tf32 GEMM (R13 configuration — known-good) ----------------
// C[R x N] = act( X @ W^T + bias ). W pre-split (wsel: 1=WT, 2=WR, 3=WL).
// Optional row gather (gsel: 1=(nl1,cnt1), 2=(nl0,cnt0)).
// 128x128 block tile, 8 warps (2m x 4n of 64x32), K_BLK=8 double-buffered pipeline.
__global__ __launch_bounds__(256) void k_gemm128t(
    const float* __restrict__ xext, int xid, int R,
    int wsel,
    const float* __restrict__ bias, int act,
    float* __restrict__ c1ext, int c1id, int c2id,
    int gsel)
{
    const float* X = xid ? dbuf(xid) : xext;
    const float2* sW0 = (wsel == 1) ? g_sWT : (wsel == 2) ? g_sWR : g_sWL;
    const int* gather = (gsel == 1) ? g_nl1 : (gsel == 2) ? g_nl0 : nullptr;

    int Reff = R;
    if (gsel == 1) Reff = g_cnt1;
    else if (gsel == 2) Reff = g_cnt0;

    const int r0 = blockIdx.x * 128;
    if (r0 >= Reff) return;
    const int j0 = blockIdx.y * 128;

    __shared__ float2 Xs[2][8][SP2];
    __shared__ float2 Wsh[2][8][SP2];

    float* Cbase;
    if (c1id == 0 && c2id == 0) Cbase = c1ext + j0;
    else Cbase = (j0 < 256) ? (dbuf(c1id) + j0) : (dbuf(c2id) + (j0 - 256));

    const int tid = threadIdx.x;
    const int wid = tid >> 5;
    const int lane = tid & 31;
    const int m0 = (wid >> 2) * 64;
    const int n0 = (wid & 3) * 32;
    const int g = lane >> 2;
    const int t4 = lane & 3;

    const int row = tid >> 1;
    const int kq = (tid & 1) << 2;
    const int lrow = r0 + row;
    const bool xok = lrow < Reff;
    int grow = lrow;
    if (gather && xok) grow = gather[lrow];
    const float* Xrow = X + (size_t)grow * D + kq;
    const float2* Wrow = sW0 + (size_t)(j0 + row) * D + kq;

    float c[4][4][4];
#pragma unroll
    for (int mi = 0; mi < 4; mi++)
#pragma unroll
        for (int nj = 0; nj < 4; nj++)
#pragma unroll
            for (int k = 0; k < 4; k++) c[mi][nj][k] = 0.f;

    float4 xv = make_float4(0.f, 0.f, 0.f, 0.f);
    float4 wa, wb;

    if (xok) xv = *(const float4*)(Xrow);
    wa = ((const float4*)Wrow)[0];
    wb = ((const float4*)Wrow)[1];
    Xs[0][kq + 0][row] = splitpack(xv.x); Xs[0][kq + 1][row] = splitpack(xv.y);
    Xs[0][kq + 2][row] = splitpack(xv.z); Xs[0][kq + 3][row] = splitpack(xv.w);
    Wsh[0][kq + 0][row] = make_float2(wa.x, wa.y);
    Wsh[0][kq + 1][row] = make_float2(wa.z, wa.w);
    Wsh[0][kq + 2][row] = make_float2(wb.x, wb.y);
    Wsh[0][kq + 3][row] = make_float2(wb.z, wb.w);
    __syncthreads();

    for (int kb = 0; kb < 32; kb++) {
        const int cur = kb & 1, nxt = cur ^ 1;
        if (kb < 31) {
            int k0 = (kb + 1) * 8;
            xv = make_float4(0.f, 0.f, 0.f, 0.f);
            if (xok) xv = *(const float4*)(Xrow + k0);
            wa = ((const float4*)(Wrow + k0))[0];
            wb = ((const float4*)(Wrow + k0))[1];
        }
        {
            float2 b0[4], b1[4];
#pragma unroll
            for (int nj = 0; nj < 4; nj++) {
                int nc = n0 + nj * 8 + g;
                b0[nj] = Wsh[cur][t4][nc];
                b1[nj] = Wsh[cur][4 + t4][nc];
            }
#pragma unroll
            for (int mi = 0; mi < 4; mi++) {
                int mr = m0 + mi * 16;
                float2 a0 = Xs[cur][t4][mr + g];
                float2 a1 = Xs[cur][t4][mr + 8 + g];
                float2 a2 = Xs[cur][4 + t4][mr + g];
                float2 a3 = Xs[cur][4 + t4][mr + 8 + g];
                unsigned ah0 = __float_as_uint(a0.x), al0 = __float_as_uint(a0.y);
                unsigned ah1 = __float_as_uint(a1.x), al1 = __float_as_uint(a1.y);
                unsigned ah2 = __float_as_uint(a2.x), al2 = __float_as_uint(a2.y);
                unsigned ah3 = __float_as_uint(a3.x), al3 = __float_as_uint(a3.y);
#pragma unroll
                for (int nj = 0; nj < 4; nj++) {
                    unsigned bh0 = __float_as_uint(b0[nj].x), bl0 = __float_as_uint(b0[nj].y);
                    unsigned bh1 = __float_as_uint(b1[nj].x), bl1 = __float_as_uint(b1[nj].y);
                    mma_tf32(c[mi][nj], al0, al1, al2, al3, bh0, bh1);
                    mma_tf32(c[mi][nj], ah0, ah1, ah2, ah3, bl0, bl1);
                    mma_tf32(c[mi][nj], ah0, ah1, ah2, ah3, bh0, bh1);
                }
            }
        }
        if (kb < 31) {
            Xs[nxt][kq + 0][row] = splitpack(xv.x); Xs[nxt][kq + 1][row] = splitpack(xv.y);
            Xs[nxt][kq + 2][row] = splitpack(xv.z); Xs[nxt][kq + 3][row] = splitpack(xv.w);
            Wsh[nxt][kq + 0][row] = make_float2(wa.x, wa.y);
            Wsh[nxt][kq + 1][row] = make_float2(wa.z, wa.w);
            Wsh[nxt][kq + 2][row] = make_float2(wb.x, wb.y);
            Wsh[nxt][kq + 3][row] = make_float2(wb.z, wb.w);
        }
        __syncthreads();
    }

#pragma unroll
    for (int mi = 0; mi < 4; mi++) {
#pragma unroll
        for (int half = 0; half < 2; half++) {
            int orow = r0 + m0 + mi * 16 + half * 8 + g;
            if (orow < Reff) {
#pragma unroll
                for (int nj = 0; nj < 4; nj++) {
                    int col = n0 + nj * 8 + t4 * 2;
                    float v0 = c[mi][nj][half * 2 + 0];
                    float v1 = c[mi][nj][half * 2 + 1];
                    if (bias) { v0 += bias[j0 + col]; v1 += bias[j0 + col + 1]; }
                    if (act) {
                        v0 = v0 > 0.f ? v0 : 0.01f * v0;
                        v1 = v1 > 0.f ? v1 : 0.01f * v1;
                    }
                    *(float2*)(Cbase + (size_t)orow * D + col) = make_float2(v0, v1);
                }
            }
        }
    }
}

// g_M = A^T * B (A, B 1024x1024 row-major), fp32 SIMT
__global__ __launch_bounds__(256) void k_gemm128_tn(const float* __restrict__ A,
                                                    const float* __restrict__ B) {
    __shared__ float As[2][16][SPAD];
    __shared__ float Bs[2][16][SPAD];

    const int i0 = blockIdx.x * 128;
    const int j0 = blockIdx.y * 128;
    const int tid = threadIdx.x;
    const int tx = tid & 15, ty = tid >> 4;

    float acc[8][8];
#pragma unroll
    for (int r = 0; r < 8; r++)
#pragma unroll
        for (int c = 0; c < 8; c++) acc[r][c] = 0.f;

    float4 xs[2], ws[2];

#pragma unroll
    for (int i = 0; i < 2; i++) {
        int f = tid + i * 256;
        int i4 = (f & 31) << 2, kk = f >> 5;
        *(float4*)&As[0][kk][i4] = *(const float4*)(A + (size_t)kk * D4 + i0 + i4);
        *(float4*)&Bs[0][kk][i4] = *(const float4*)(B + (size_t)kk * D4 + j0 + i4);
    }
    __syncthreads();

    for (int kb = 0; kb < 64; kb++) {
        int cur = kb & 1, nxt = cur ^ 1;
        if (kb < 63) {
            int k0 = (kb + 1) * 16;
#pragma unroll
            for (int i = 0; i < 2; i++) {
                int f = tid + i * 256;
                int i4 = (f & 31) << 2, kk = f >> 5;
                xs[i] = *(const float4*)(A + (size_t)(k0 + kk) * D4 + i0 + i4);
                ws[i] = *(const float4*)(B + (size_t)(k0 + kk) * D4 + j0 + i4);
            }
        }
#pragma unroll
        for (int kk = 0; kk < 16; kk++) {
            float a[8], b[8];
            *(float4*)&a[0] = *(const float4*)&As[cur][kk][ty * 8];
            *(float4*)&a[4] = *(const float4*)&As[cur][kk][ty * 8 + 4];
            *(float4*)&b[0] = *(const float4*)&Bs[cur][kk][tx * 8];
            *(float4*)&b[4] = *(const float4*)&Bs[cur][kk][tx * 8 + 4];
#pragma unroll
            for (int r = 0; r < 8; r++)
#pragma unroll
                for (int c = 0; c < 8; c++) acc[r][c] += a[r] * b[c];
        }
        if (kb < 63) {
#pragma unroll
            for (int i = 0; i < 2; i++) {
                int f = tid + i * 256;
                int i4 = (f & 31) << 2, kk = f >> 5;
                *(float4*)&As[nxt][kk][i4] = xs[i];
                *(float4*)&Bs[nxt][kk][i4] = ws[i];
            }
            __syncthreads();
        }
    }

#pragma unroll
    for (int r = 0; r < 8; r++) {
        float* crow = g_M + (size_t)(i0 + ty * 8 + r) * D4 + j0 + tx * 8;
        *(float4*)crow = *(float4*)&acc[r][0];
        *(float4*)(crow + 4) = *(float4*)&acc[r][4];
    }
}

// pre-split W into packed float2(hi,lo)
__global__ void k_splitw(const float* __restrict__ ext, int mode) {
    int i = blockIdx.x * blockDim.x + threadIdx.x;
    int total = (mode == 3 ? 256 : 512) * D;
    if (i >= total) return;
    int r = i >> 8, cidx = i & 255;
    float v;
    if (mode == 1) v = g_M[(size_t)r * D4 + cidx];
    else if (mode == 2) v = g_M[(size_t)r * D4 + 256 + cidx];
    else v = ext[i];
    float2 p = splitpack(v);
    if (mode == 1) g_sWT[i] = p;
    else if (mode == 2) g_sWR[i] = p;
    else g_sWL[i] = p;
}

// edges are int32 rows of stride s32; field f at f*fm
__global__ void k_extract(const int* __restrict__ e1, const int* __restrict__ e0,
                          int s32, int fm) {
    int i = blockIdx.x * blockDim.x + threadIdx.x;
    if (i < E1C) {
        int q = e1[(size_t)i * s32 + 0 * fm];
        int s = e1[(size_t)i * s32 + 6 * fm];
        int d = e1[(size_t)i * s32 + 7 * fm];
        g_q1[i] = ((unsigned)q < NQ) ? q : 0;
        g_s1[i] = ((unsigned)s < N_NODES) ? s : 0;
        g_d1[i] = ((unsigned)d < N_NODES) ? d : 0;
    }
    if (i < E0C) {
        int q = e0[(size_t)i * s32 + 0 * fm];
        int s = e0[(size_t)i * s32 + 6 * fm];
        int d = e0[(size_t)i * s32 + 7 * fm];
        g_q0[i] = ((unsigned)q < NQ) ? q : 0;
        g_s0[i] = ((unsigned)s < N_NODES) ? s : 0;
        g_d0[i] = ((unsigned)d < N_NODES) ? d : 0;
    }
}

// dst-set compaction
__global__ void k_markinit() {
    int i = blockIdx.x * blockDim.x + threadIdx.x;
    if (i < N_NODES) { g_need1[i] = 0; g_need0[i] = 0; }
    if (i == 0) { g_cnt1 = 0; g_cnt0 = 0; }
}
__global__ void k_mark() {
    int i = blockIdx.x * blockDim.x + threadIdx.x;
    if (i < E1C) g_need1[g_d1[i]] = 1;
    if (i < E0C) g_need0[g_d0[i]] = 1;
}
__global__ void k_compact() {
    int i = blockIdx.x * blockDim.x + threadIdx.x;
    if (i < N_NODES) {
        if (g_need1[i]) { int p = atomicAdd(&g_cnt1, 1); g_cid1[i] = p; g_nl1[p] = i; }
        if (g_need0[i]) { int p = atomicAdd(&g_cnt0, 1); g_cid0[i] = p; g_nl0[p] = i; }
    }
}

// per-query vectors from blocks of M = Wq^T Wk
__global__ void k_queryvec(const float* __restrict__ qst, const float* __restrict__ qr) {
    int q = blockIdx.x;
    int j = threadIdx.x;
    __shared__ float ss[256], tt[256], red[256];
    ss[j] = qst[q * D + j];
    tt[j] = qr[q * D + j];
    __syncthreads();
    int which = blockIdx.y;
    if (which == 0) {
        const float* row = g_M + (size_t)j * D4;
        float a = 0.f;
        for (int k = 0; k < D; k++) a += row[512 + k] * ss[k] + row[768 + k] * tt[k];
        g_v[q * D + j] = a;
    } else if (which == 1) {
        const float* row = g_M + (size_t)(256 + j) * D4;
        float a = 0.f;
        for (int k = 0; k < D; k++) a += row[512 + k] * ss[k] + row[768 + k] * tt[k];
        for (int k = 0; k < D; k++)
            a += g_M[(size_t)(512 + k) * D4 + 256 + j] * ss[k]
               + g_M[(size_t)(768 + k) * D4 + 256 + j] * tt[k];
        g_wz[q * D + j] = a;
    } else if (which == 2) {
        float a = 0.f;
        for (int k = 0; k < D; k++)
            a += g_M[(size_t)(512 + k) * D4 + j] * ss[k]
               + g_M[(size_t)(768 + k) * D4 + j] * tt[k];
        g_u[q * D + j] = a;
    } else {
        const float* rs = g_M + (size_t)(512 + j) * D4;
        const float* rt = g_M + (size_t)(768 + j) * D4;
        float ps = 0.f, pt = 0.f;
        for (int k = 0; k < D; k++) {
            ps += rs[512 + k] * ss[k] + rs[768 + k] * tt[k];
            pt += rt[512 + k] * ss[k] + rt[768 + k] * tt[k];
        }
        red[j] = ss[j] * ps + tt[j] * pt;
        __syncthreads();
        for (int s = 128; s; s >>= 1) {
            if (j < s) red[j] += red[j + s];
            __syncthreads();
        }
        if (j == 0) g_c[q] = red[0];
    }
}

// one warp per edge; each lane owns a contiguous 8-float span (2x float4 per operand)
__global__ void k_edge_score(int pass, int nrid, const float* __restrict__ nrext,
                             const float* __restrict__ rel, int ne) {
    int e = blockIdx.x * 8 + (threadIdx.x >> 5);
    if (e >= ne) return;
    int lane = threadIdx.x & 31;
    const int* qs = pass ? g_q1 : g_q0;
    const int* ssrc = pass ? g_s1 : g_s0;
    const int* sdst = pass ? g_d1 : g_d0;
    const int* cid = pass ? g_cid1 : g_cid0;
    const float* NR = nrid ? dbuf(nrid) : nrext;
    int q = qs[e], s = ssrc[e], d = sdst[e];
    int cd = cid[d];
    int kb = lane * 8;
    const float* ns = NR + (size_t)s * D + kb;
    const float* nd = NR + (size_t)d * D + kb;
    const float* re = rel + (size_t)e * D + kb;
    const float* t1 = g_T1 + (size_t)cd * D + kb;
    const float* t2 = g_T2 + (size_t)cd * D + kb;
    const float* r1 = g_R1 + (size_t)e * D + kb;
    const float* r2 = g_R2 + (size_t)e * D + kb;
    const float* vq = g_v + q * D + kb;
    const float* wq = g_wz + q * D + kb;
    const float* uq = g_u + q * D + kb;
    float a = 0.f;
#pragma unroll
    for (int h = 0; h < 8; h += 4) {
        float4 xn = *(const float4*)(ns + h);
        float4 xt1 = *(const float4*)(t1 + h);
        float4 xr1 = *(const float4*)(r1 + h);
        float4 xv = *(const float4*)(vq + h);
        a += xn.x * (xt1.x + xr1.x + xv.x) + xn.y * (xt1.y + xr1.y + xv.y)
           + xn.z * (xt1.z + xr1.z + xv.z) + xn.w * (xt1.w + xr1.w + xv.w);
        float4 xe = *(const float4*)(re + h);
        float4 xt2 = *(const float4*)(t2 + h);
        float4 xr2 = *(const float4*)(r2 + h);
        float4 xw = *(const float4*)(wq + h);
        a += xe.x * (xt2.x + xr2.x + xw.x) + xe.y * (xt2.y + xr2.y + xw.y)
           + xe.z * (xt2.z + xr2.z + xw.z) + xe.w * (xt2.w + xr2.w + xw.w);
        float4 xd = *(const float4*)(nd + h);
        float4 xu = *(const float4*)(uq + h);
        a += xd.x * xu.x + xd.y * xu.y + xd.z * xu.z + xd.w * xu.w;
    }
#pragma unroll
    for (int o = 16; o; o >>= 1) a += __shfl_xor_sync(0xffffffffu, a, o);
    if (lane == 0) g_logits[e] = a + g_c[q];
}

__global__ void k_seg_init() {
    int i = blockIdx.x * blockDim.x + threadIdx.x;
    if (i < N_NODES) {
        g_segmax[i] = 0u;
        g_segsum[i] = 0.f;
        g_flag[i] = 0;
    }
}

__global__ void k_seg_max(int pass, int ne) {
    int i = blockIdx.x * blockDim.x + threadIdx.x;
    if (i < ne) {
        const int* seg = pass ? g_s1 : g_s0;
        atomicMax(&g_segmax[seg[i]], fenc(g_logits[i]));
    }
}

__global__ void k_seg_exp(int pass, int ne) {
    int i = blockIdx.x * blockDim.x + threadIdx.x;
    if (i < ne) {
        const int* seg = pass ? g_s1 : g_s0;
        float m = fdec(g_segmax[seg[i]]);
        float e = expf(g_logits[i] - m);
        g_exp[i] = e;
        atomicAdd(&g_segsum[seg[i]], e);
    }
}

// per-query bitonic sort of 256 (target, idx); target computed inline from exp/segsum*vscore
__global__ void k_topk(const int* __restrict__ edges1, int s32, int fm,
                       const float* __restrict__ vscore,
                       float* __restrict__ out_pe, float* __restrict__ out_oi) {
    int q = blockIdx.x;
    int t = threadIdx.x;
    __shared__ float sv[256];
    __shared__ int si[256];
    {
        int e = q * PG + t;
        int s = g_s1[e];
        float sft = g_exp[e] / g_segsum[s];
        sv[t] = sft * vscore[s];
    }
    si[t] = t;
    __syncthreads();
    for (int k = 2; k <= 256; k <<= 1) {
        for (int j = k >> 1; j > 0; j >>= 1) {
            int ixj = t ^ j;
            if (ixj > t) {
                float va = sv[t], vb = sv[ixj];
                int ia = si[t], ib = si[ixj];
                bool before = (va > vb) || (va == vb && ia < ib);
                bool up = ((t & k) == 0);
                if (up ? !before : before) {
                    sv[t] = vb; sv[ixj] = va;
                    si[t] = ib; si[ixj] = ia;
                }
            }
            __syncthreads();
        }
    }
    if (t < ME) {
        int oi = q * PG + si[t];
        int po = q * ME + t;
        out_oi[po] = (float)oi;
#pragma unroll
        for (int f = 0; f < 8; f++)
            out_pe[(size_t)po * 8 + f] = (float)edges1[(size_t)oi * s32 + f * fm];
        int s = edges1[(size_t)oi * s32 + 6 * fm];
        int d = edges1[(size_t)oi * s32 + 7 * fm];
        s = ((unsigned)s < N_NODES) ? s : 0;
        d = ((unsigned)d < N_NODES) ? d : 0;
        g_psrc[po] = s;
        g_pdst[po] = d;
        g_psoft[po] = g_exp[oi] / g_segsum[g_s1[oi]];
        g_ptgt[po] = sv[t];
    }
}

__global__ void k_zero_score(float* __restrict__ out_score) {
    int i = blockIdx.x * blockDim.x + threadIdx.x;
    if (i < N_NODES) out_score[i] = 0.f;
}

__global__ void k_scatter_score_flag(float* __restrict__ out_score) {
    int i = blockIdx.x * blockDim.x + threadIdx.x;
    if (i < NQ * ME) {
        atomicAdd(&out_score[g_pdst[i]], g_ptgt[i]);
        g_flag[g_psrc[i]] = 1;
    }
}

__global__ void k_set_flag0() {
    int i = blockIdx.x * blockDim.x + threadIdx.x;
    if (i < E0C) g_flag[g_s0[i]] = 1;
}

// mode 0: out = g_NR1, in = external NR ; mode 1: out = g_NR2, in = g_NR1
__global__ void k_scale_repr(int mode, const float* __restrict__ nrext) {
    size_t i = (size_t)blockIdx.x * blockDim.x + threadIdx.x;
    if (i < (size_t)N_NODES * (D / 4)) {
        const float4* in = mode ? (const float4*)g_NR1 : (const float4*)nrext;
        float4* out = mode ? (float4*)g_NR2 : (float4*)g_NR1;
        int n = (int)(i >> 6);
        float sc = g_flag[n] ? 0.2f : 1.0f;
        float4 vv = in[i];
        vv.x *= sc; vv.y *= sc; vv.z *= sc; vv.w *= sc;
        out[i] = vv;
    }
}

// mode 0: pruned edges (weight = g_psoft), base external NR, acc g_NR1
// mode 1: edges0 (weight = exp/segsum computed inline), base g_NR1, acc g_NR2
__global__ void k_edge_agg(int mode, const float* __restrict__ nrext, int ne) {
    int e = blockIdx.x * 8 + (threadIdx.x >> 5);
    if (e >= ne) return;
    int lane = threadIdx.x & 31;
    const int* src = mode ? g_s0 : g_psrc;
    const int* dst = mode ? g_d0 : g_pdst;
    const float* base = mode ? g_NR1 : nrext;
    float* acc = mode ? g_NR2 : g_NR1;
    float w;
    if (mode) w = g_exp[e] / g_segsum[src[e]];
    else w = g_psoft[e];
    float cf = 0.8f * w;
    const float* bd = base + (size_t)dst[e] * D;
    float* as = acc + (size_t)src[e] * D;
#pragma unroll
    for (int i = 0; i < 8; i++) atomicAdd(as + lane + 32 * i, cf * bd[lane + 32 * i]);
}

// ---------------- host: kernel launches ONLY ----------------
extern "C" void kernel_launch(void* const* d_in, const int* in_sizes, int n_in,
                              void* d_out, int out_size) {
    int iVS = -1, iNR = -1, iE0 = -1, iE1 = -1, iR0 = -1, iR1 = -1;
    int iQA = -1, iQB = -1, iWA = -1, iWB = -1, iWL = -1, iBL = -1;
    for (int i = 0; i < n_in; i++) {
        long sz = in_sizes[i];
        if (sz == 50000) iVS = i;
        else if (sz == 12800000) iNR = i;
        else if (sz == 262144 || sz == 524288) { if (iE0 < 0) iE0 = i; else iE1 = i; }
        else if (sz == 8388608) { if (iR0 < 0) iR0 = i; else iR1 = i; }
        else if (sz == 32768) { if (iQA < 0) iQA = i; else iQB = i; }
        else if (sz == 1048576) { if (iWA < 0) iWA = i; else iWB = i; }
        else if (sz == 65536) iWL = i;
        else if (sz == 256) iBL = i;
    }
    bool dictOrder = (in_sizes[0] == 50000);

    const float* vscore = (const float*)d_in[iVS];
    const float* NR = (const float*)d_in[iNR];
    const int* e0 = (const int*)d_in[iE0];
    const int* e1 = (const int*)d_in[iE1];
    const float* rel0 = (const float*)d_in[iR0];
    const float* rel1 = (const float*)d_in[iR1];
    const float* qst = (const float*)d_in[dictOrder ? iQA : iQB];
    const float* qr = (const float*)d_in[dictOrder ? iQB : iQA];
    const float* Wq = (const float*)d_in[dictOrder ? iWA : iWB];
    const float* Wk = (const float*)d_in[dictOrder ? iWB : iWA];
    const float* Wl = (const float*)d_in[iWL];
    const float* bl = (const float*)d_in[iBL];

    int s32 = in_sizes[iE0] / 32768;
    int fm = s32 >> 3;

    float* out = (float*)d_out;
    float* out_score = out;
    float* out_repr = out + N_NODES;
    float* out_pe = out_repr + (size_t)N_NODES * D;
    float* out_oi = out_pe + (size_t)NQ * ME * 8;

    const int NB50K = (N_NODES + 255) / 256;
    const int GRN = (N_NODES + 127) / 128;   // 391
    const int GRE = E1C / 128;               // 256

    k_extract<<<128, 256>>>(e1, e0, s32, fm);
    k_markinit<<<NB50K, 256>>>();
    k_mark<<<128, 256>>>();
    k_compact<<<NB50K, 256>>>();
    k_gemm128_tn<<<dim3(8, 8), 256>>>(Wq, Wk);
    k_splitw<<<512, 256>>>(nullptr, 1);
    k_splitw<<<512, 256>>>(nullptr, 2);
    k_splitw<<<256, 256>>>(Wl, 3);
    k_queryvec<<<dim3(NQ, 4), 256>>>(qst, qr);

    // ---- pass 1 tables: T (compacted dst1 rows) and R (all edges), split-tf32 ----
    k_gemm128t<<<dim3(GRN, 4), 256>>>(NR, 0, N_NODES, 1, nullptr, 0, nullptr, BUF_T1, BUF_T2, 1);
    k_gemm128t<<<dim3(GRE, 4), 256>>>(rel1, 0, E1C, 2, nullptr, 0, nullptr, BUF_R1, BUF_R2, 0);

    // ---- pass 1 scores + segment softmax ----
    k_seg_init<<<NB50K, 256>>>();
    k_edge_score<<<E1C / 8, 256>>>(1, 0, NR, rel1, E1C);
    k_seg_max<<<128, 256>>>(1, E1C);
    k_seg_exp<<<128, 256>>>(1, E1C);

    // ---- top-64 per query (computes target + psoft inline) ----
    k_topk<<<NQ, 256>>>(e1, s32, fm, vscore, out_pe, out_oi);

    // ---- updated node score + repr update 1 ----
    k_zero_score<<<NB50K, 256>>>(out_score);
    k_scatter_score_flag<<<(NQ * ME + 255) / 256, 256>>>(out_score);
    k_scale_repr<<<(N_NODES * (D / 4) + 255) / 256, 256>>>(0, NR);
    k_edge_agg<<<NQ * ME / 8, 256>>>(0, NR, NQ * ME);

    // ---- pass 2 tables (compacted dst0 rows) ----
    k_gemm128t<<<dim3(GRN, 4), 256>>>(nullptr, BUF_NR1, N_NODES, 1, nullptr, 0, nullptr, BUF_T1, BUF_T2, 2);
    k_gemm128t<<<dim3(GRE, 4), 256>>>(rel0, 0, E0C, 2, nullptr, 0, nullptr, BUF_R1, BUF_R2, 0);

    // ---- pass 2 scores + softmax ----
    k_seg_init<<<NB50K, 256>>>();
    k_edge_score<<<E0C / 8, 256>>>(0, BUF_NR1, nullptr, rel0, E0C);
    k_seg_max<<<128, 256>>>(0, E0C);
    k_seg_exp<<<128, 256>>>(0, E0C);

    // ---- repr update 2 (softmax weight computed inline in edge_agg) ----
    k_set_flag0<<<128, 256>>>();
    k_scale_repr<<<(N_NODES * (D / 4) + 255) / 256, 256>>>(1, nullptr);
    k_edge_agg<<<E0C / 8, 256>>>(1, nullptr, E0C);

    // ---- final linear layer + leaky relu (N=256 external out, full node set) ----
    k_gemm128t<<<dim3(GRN, 2), 256>>>(nullptr, BUF_NR2, N_NODES, 3, bl, 1, out_repr, 0, 0, 0);
}

// round 16
// speedup vs baseline: 1.1521x; 1.0506x over previous
#include <cuda_runtime.h>
#include <math.h>

#define N_NODES 50000
#define D 256
#define D4 1024
#define NQ 128
#define PG 256
#define E1C 32768
#define E0C 32768
#define ME 64
#define SPAD 132
#define SP2 132

// ---------------- scratch (static device globals; referenced ONLY from device code) ----------------
__device__ __align__(16) float g_M[D4 * D4];   // Wq^T Wk
__device__ __align__(16) float g_v[NQ * D];
__device__ __align__(16) float g_wz[NQ * D];
__device__ __align__(16) float g_u[NQ * D];
__device__ float g_c[NQ];
__device__ __align__(16) float g_T1[N_NODES * D];
__device__ __align__(16) float g_T2[N_NODES * D];
__device__ __align__(16) float g_T1b[N_NODES * D];   // pass-2 fresh rows
__device__ __align__(16) float g_T2b[N_NODES * D];
__device__ __align__(16) float g_R1[E1C * D];
__device__ __align__(16) float g_R2[E1C * D];
__device__ float g_logits[E1C];
__device__ float g_exp[E1C];
__device__ unsigned g_segmax[N_NODES];
__device__ float g_segsum[N_NODES];
__device__ int g_flag[N_NODES];
__device__ __align__(16) float g_NR1[N_NODES * D];
__device__ __align__(16) float g_NR2[N_NODES * D];
__device__ int g_s1[E1C], g_d1[E1C], g_q1[E1C];
__device__ int g_s0[E0C], g_d0[E0C], g_q0[E0C];
__device__ int g_psrc[NQ * ME], g_pdst[NQ * ME];
__device__ float g_psoft[NQ * ME], g_ptgt[NQ * ME];

// compaction of dst-node sets
__device__ int g_need1[N_NODES], g_need0[N_NODES];
__device__ int g_cid1[N_NODES];
__device__ int g_nl1[N_NODES];
__device__ int g_cnt1;
// pass-2 incremental set: dst0 rows needing fresh compute (flagged or not in dst1)
__device__ int g_selN[N_NODES], g_cidN[N_NODES], g_nlN[N_NODES];
__device__ int g_cntN;

// pre-split W operands: packed float2(hi,lo) per element, row-major [row][k]
__device__ __align__(16) float2 g_sWT[512 * D];
__device__ __align__(16) float2 g_sWR[512 * D];
__device__ __align__(16) float2 g_sWL[256 * D];

#define BUF_T1 1
#define BUF_T2 2
#define BUF_R1 3
#define BUF_R2 4
#define BUF_NR1 5
#define BUF_NR2 6
#define BUF_T1B 7
#define BUF_T2B 8

__device__ __forceinline__ float* dbuf(int id) {
    switch (id) {
        case BUF_T1: return g_T1;
        case BUF_T2: return g_T2;
        case BUF_R1: return g_R1;
        case BUF_R2: return g_R2;
        case BUF_NR1: return g_NR1;
        case BUF_T1B: return g_T1b;
        case BUF_T2B: return g_T2b;
        default: return g_NR2;
    }
}

__device__ __forceinline__ unsigned fenc(float f) {
    unsigned u = __float_as_uint(f);
    return (u & 0x80000000u) ? ~u : (u | 0x80000000u);
}
__device__ __forceinline__ float fdec(unsigned e) {
    return __uint_as_float((e & 0x80000000u) ? (e ^ 0x80000000u) : ~e);
}

__device__ __forceinline__ unsigned f2tf32(float x) {
    unsigned r;
    asm("cvt.rna.tf32.f32 %0, %1;" : "=r"(r) : "f"(x));
    return r;
}

__device__ __forceinline__ void mma_tf32(float* c, unsigned a0, unsigned a1, unsigned a2,
                                         unsigned a3, unsigned b0, unsigned b1) {
    asm volatile(
        "mma.sync.aligned.m16n8k8.row.col.f32.tf32.tf32.f32 "
        "{%0,%1,%2,%3}, {%4,%5,%6,%7}, {%8,%9}, {%0,%1,%2,%3};"
        : "+f"(c[0]), "+f"(c[1]), "+f"(c[2]), "+f"(c[3])
        : "r"(a0), "r"(a1), "r"(a2), "r"(a3), "r"(b0), "r"(b1));
}

__device__ __forceinline__ float2 splitpack(float v) {
    unsigned h = f2tf32(v);
    unsigned l = f2tf32(v - __uint_as_float(h));
    return make_float2(__uint_as_float(h), __uint_as_float(l));
}

// ---------------- dual-part tensor-core split-tf32 GEMM ----------------
// Two independent GEMM parts in ONE launch (wave smoothing): x-blocks [0,splitX) run
// part A, the rest part B. Each part: C[R x 512] = X @ W^T (cols 0..255 -> c1, 256..511 -> c2).
// W pre-split (wsel 1=WT, 2=WR, 3=WL). gsel: 0 none, 1 gather nl1/cnt1, 3 gather nlN/cntN.
// If c1==0 && c2==0 -> external output cext (+bias/act), N given by gridDim.y*128.
// Core: 128x128 block tile, 8 warps (2m x 4n of 64x32), K_BLK=8 double-buffered pipeline.
__global__ __launch_bounds__(256) void k_gemm_dual(
    const float* __restrict__ xA, int xidA, int RA, int wselA, int gselA, int c1A, int c2A,
    const float* __restrict__ xB, int xidB, int RB, int wselB, int gselB, int c1B, int c2B,
    int splitX,
    const float* __restrict__ bias, int act, float* __restrict__ cext)
{
    const bool isA = (int)blockIdx.x < splitX;
    const int bx = isA ? blockIdx.x : (blockIdx.x - splitX);
    const float* xext = isA ? xA : xB;
    const int xid = isA ? xidA : xidB;
    const int R = isA ? RA : RB;
    const int wsel = isA ? wselA : wselB;
    const int gsel = isA ? gselA : gselB;
    const int c1id = isA ? c1A : c1B;
    const int c2id = isA ? c2A : c2B;

    const float* X = xid ? dbuf(xid) : xext;
    const float2* sW0 = (wsel == 1) ? g_sWT : (wsel == 2) ? g_sWR : g_sWL;
    const int* gather = (gsel == 1) ? g_nl1 : (gsel == 3) ? g_nlN : nullptr;

    int Reff = R;
    if (gsel == 1) Reff = g_cnt1;
    else if (gsel == 3) Reff = g_cntN;

    const int r0 = bx * 128;
    if (r0 >= Reff) return;
    const int j0 = blockIdx.y * 128;

    __shared__ float2 Xs[2][8][SP2];
    __shared__ float2 Wsh[2][8][SP2];

    float* Cbase;
    if (c1id == 0 && c2id == 0) Cbase = cext + j0;
    else Cbase = (j0 < 256) ? (dbuf(c1id) + j0) : (dbuf(c2id) + (j0 - 256));

    const int tid = threadIdx.x;
    const int wid = tid >> 5;
    const int lane = tid & 31;
    const int m0 = (wid >> 2) * 64;
    const int n0 = (wid & 3) * 32;
    const int g = lane >> 2;
    const int t4 = lane & 3;

    const int row = tid >> 1;
    const int kq = (tid & 1) << 2;
    const int lrow = r0 + row;
    const bool xok = lrow < Reff;
    int grow = lrow;
    if (gather && xok) grow = gather[lrow];
    const float* Xrow = X + (size_t)grow * D + kq;
    const float2* Wrow = sW0 + (size_t)(j0 + row) * D + kq;

    float c[4][4][4];
#pragma unroll
    for (int mi = 0; mi < 4; mi++)
#pragma unroll
        for (int nj = 0; nj < 4; nj++)
#pragma unroll
            for (int k = 0; k < 4; k++) c[mi][nj][k] = 0.f;

    float4 xv = make_float4(0.f, 0.f, 0.f, 0.f);
    float4 wa, wb;

    if (xok) xv = *(const float4*)(Xrow);
    wa = ((const float4*)Wrow)[0];
    wb = ((const float4*)Wrow)[1];
    Xs[0][kq + 0][row] = splitpack(xv.x); Xs[0][kq + 1][row] = splitpack(xv.y);
    Xs[0][kq + 2][row] = splitpack(xv.z); Xs[0][kq + 3][row] = splitpack(xv.w);
    Wsh[0][kq + 0][row] = make_float2(wa.x, wa.y);
    Wsh[0][kq + 1][row] = make_float2(wa.z, wa.w);
    Wsh[0][kq + 2][row] = make_float2(wb.x, wb.y);
    Wsh[0][kq + 3][row] = make_float2(wb.z, wb.w);
    __syncthreads();

    for (int kb = 0; kb < 32; kb++) {
        const int cur = kb & 1, nxt = cur ^ 1;
        if (kb < 31) {
            int k0 = (kb + 1) * 8;
            xv = make_float4(0.f, 0.f, 0.f, 0.f);
            if (xok) xv = *(const float4*)(Xrow + k0);
            wa = ((const float4*)(Wrow + k0))[0];
            wb = ((const float4*)(Wrow + k0))[1];
        }
        {
            float2 b0[4], b1[4];
#pragma unroll
            for (int nj = 0; nj < 4; nj++) {
                int nc = n0 + nj * 8 + g;
                b0[nj] = Wsh[cur][t4][nc];
                b1[nj] = Wsh[cur][4 + t4][nc];
            }
#pragma unroll
            for (int mi = 0; mi < 4; mi++) {
                int mr = m0 + mi * 16;
                float2 a0 = Xs[cur][t4][mr + g];
                float2 a1 = Xs[cur][t4][mr + 8 + g];
                float2 a2 = Xs[cur][4 + t4][mr + g];
                float2 a3 = Xs[cur][4 + t4][mr + 8 + g];
                unsigned ah0 = __float_as_uint(a0.x), al0 = __float_as_uint(a0.y);
                unsigned ah1 = __float_as_uint(a1.x), al1 = __float_as_uint(a1.y);
                unsigned ah2 = __float_as_uint(a2.x), al2 = __float_as_uint(a2.y);
                unsigned ah3 = __float_as_uint(a3.x), al3 = __float_as_uint(a3.y);
#pragma unroll
                for (int nj = 0; nj < 4; nj++) {
                    unsigned bh0 = __float_as_uint(b0[nj].x), bl0 = __float_as_uint(b0[nj].y);
                    unsigned bh1 = __float_as_uint(b1[nj].x), bl1 = __float_as_uint(b1[nj].y);
                    mma_tf32(c[mi][nj], al0, al1, al2, al3, bh0, bh1);
                    mma_tf32(c[mi][nj], ah0, ah1, ah2, ah3, bl0, bl1);
                    mma_tf32(c[mi][nj], ah0, ah1, ah2, ah3, bh0, bh1);
                }
            }
        }
        if (kb < 31) {
            Xs[nxt][kq + 0][row] = splitpack(xv.x); Xs[nxt][kq + 1][row] = splitpack(xv.y);
            Xs[nxt][kq + 2][row] = splitpack(xv.z); Xs[nxt][kq + 3][row] = splitpack(xv.w);
            Wsh[nxt][kq + 0][row] = make_float2(wa.x, wa.y);
            Wsh[nxt][kq + 1][row] = make_float2(wa.z, wa.w);
            Wsh[nxt][kq + 2][row] = make_float2(wb.x, wb.y);
            Wsh[nxt][kq + 3][row] = make_float2(wb.z, wb.w);
        }
        __syncthreads();
    }

#pragma unroll
    for (int mi = 0; mi < 4; mi++) {
#pragma unroll
        for (int half = 0; half < 2; half++) {
            int orow = r0 + m0 + mi * 16 + half * 8 + g;
            if (orow < Reff) {
#pragma unroll
                for (int nj = 0; nj < 4; nj++) {
                    int col = n0 + nj * 8 + t4 * 2;
                    float v0 = c[mi][nj][half * 2 + 0];
                    float v1 = c[mi][nj][half * 2 + 1];
                    if (bias) { v0 += bias[j0 + col]; v1 += bias[j0 + col + 1]; }
                    if (act) {
                        v0 = v0 > 0.f ? v0 : 0.01f * v0;
                        v1 = v1 > 0.f ? v1 : 0.01f * v1;
                    }
                    *(float2*)(Cbase + (size_t)orow * D + col) = make_float2(v0, v1);
                }
            }
        }
    }
}

// g_M = A^T * B (A, B 1024x1024 row-major), fp32 SIMT
__global__ __launch_bounds__(256) void k_gemm128_tn(const float* __restrict__ A,
                                                    const float* __restrict__ B) {
    __shared__ float As[2][16][SPAD];
    __shared__ float Bs[2][16][SPAD];

    const int i0 = blockIdx.x * 128;
    const int j0 = blockIdx.y * 128;
    const int tid = threadIdx.x;
    const int tx = tid & 15, ty = tid >> 4;

    float acc[8][8];
#pragma unroll
    for (int r = 0; r < 8; r++)
#pragma unroll
        for (int c = 0; c < 8; c++) acc[r][c] = 0.f;

    float4 xs[2], ws[2];

#pragma unroll
    for (int i = 0; i < 2; i++) {
        int f = tid + i * 256;
        int i4 = (f & 31) << 2, kk = f >> 5;
        *(float4*)&As[0][kk][i4] = *(const float4*)(A + (size_t)kk * D4 + i0 + i4);
        *(float4*)&Bs[0][kk][i4] = *(const float4*)(B + (size_t)kk * D4 + j0 + i4);
    }
    __syncthreads();

    for (int kb = 0; kb < 64; kb++) {
        int cur = kb & 1, nxt = cur ^ 1;
        if (kb < 63) {
            int k0 = (kb + 1) * 16;
#pragma unroll
            for (int i = 0; i < 2; i++) {
                int f = tid + i * 256;
                int i4 = (f & 31) << 2, kk = f >> 5;
                xs[i] = *(const float4*)(A + (size_t)(k0 + kk) * D4 + i0 + i4);
                ws[i] = *(const float4*)(B + (size_t)(k0 + kk) * D4 + j0 + i4);
            }
        }
#pragma unroll
        for (int kk = 0; kk < 16; kk++) {
            float a[8], b[8];
            *(float4*)&a[0] = *(const float4*)&As[cur][kk][ty * 8];
            *(float4*)&a[4] = *(const float4*)&As[cur][kk][ty * 8 + 4];
            *(float4*)&b[0] = *(const float4*)&Bs[cur][kk][tx * 8];
            *(float4*)&b[4] = *(const float4*)&Bs[cur][kk][tx * 8 + 4];
#pragma unroll
            for (int r = 0; r < 8; r++)
#pragma unroll
                for (int c = 0; c < 8; c++) acc[r][c] += a[r] * b[c];
        }
        if (kb < 63) {
#pragma unroll
            for (int i = 0; i < 2; i++) {
                int f = tid + i * 256;
                int i4 = (f & 31) << 2, kk = f >> 5;
                *(float4*)&As[nxt][kk][i4] = xs[i];
                *(float4*)&Bs[nxt][kk][i4] = ws[i];
            }
            __syncthreads();
        }
    }

#pragma unroll
    for (int r = 0; r < 8; r++) {
        float* crow = g_M + (size_t)(i0 + ty * 8 + r) * D4 + j0 + tx * 8;
        *(float4*)crow = *(float4*)&acc[r][0];
        *(float4*)(crow + 4) = *(float4*)&acc[r][4];
    }
}

// pre-split W into packed float2(hi,lo)
__global__ void k_splitw(const float* __restrict__ ext, int mode) {
    int i = blockIdx.x * blockDim.x + threadIdx.x;
    int total = (mode == 3 ? 256 : 512) * D;
    if (i >= total) return;
    int r = i >> 8, cidx = i & 255;
    float v;
    if (mode == 1) v = g_M[(size_t)r * D4 + cidx];
    else if (mode == 2) v = g_M[(size_t)r * D4 + 256 + cidx];
    else v = ext[i];
    float2 p = splitpack(v);
    if (mode == 1) g_sWT[i] = p;
    else if (mode == 2) g_sWR[i] = p;
    else g_sWL[i] = p;
}

// edges are int32 rows of stride s32; field f at f*fm
__global__ void k_extract(const int* __restrict__ e1, const int* __restrict__ e0,
                          int s32, int fm) {
    int i = blockIdx.x * blockDim.x + threadIdx.x;
    if (i < E1C) {
        int q = e1[(size_t)i * s32 + 0 * fm];
        int s = e1[(size_t)i * s32 + 6 * fm];
        int d = e1[(size_t)i * s32 + 7 * fm];
        g_q1[i] = ((unsigned)q < NQ) ? q : 0;
        g_s1[i] = ((unsigned)s < N_NODES) ? s : 0;
        g_d1[i] = ((unsigned)d < N_NODES) ? d : 0;
    }
    if (i < E0C) {
        int q = e0[(size_t)i * s32 + 0 * fm];
        int s = e0[(size_t)i * s32 + 6 * fm];
        int d = e0[(size_t)i * s32 + 7 * fm];
        g_q0[i] = ((unsigned)q < NQ) ? q : 0;
        g_s0[i] = ((unsigned)s < N_NODES) ? s : 0;
        g_d0[i] = ((unsigned)d < N_NODES) ? d : 0;
    }
}

// dst-set marking + dst1 compaction
__global__ void k_markinit() {
    int i = blockIdx.x * blockDim.x + threadIdx.x;
    if (i < N_NODES) { g_need1[i] = 0; g_need0[i] = 0; }
    if (i == 0) { g_cnt1 = 0; g_cntN = 0; }
}
__global__ void k_mark() {
    int i = blockIdx.x * blockDim.x + threadIdx.x;
    if (i < E1C) g_need1[g_d1[i]] = 1;
    if (i < E0C) g_need0[g_d0[i]] = 1;
}
__global__ void k_compact() {
    int i = blockIdx.x * blockDim.x + threadIdx.x;
    if (i < N_NODES) {
        if (g_need1[i]) { int p = atomicAdd(&g_cnt1, 1); g_cid1[i] = p; g_nl1[p] = i; }
    }
}
// pass-2 incremental set: dst0 rows whose T must be freshly computed from NR1
// (node updated by repr-update-1 (flag) OR not present in pass-1 table).
// Runs AFTER k_scatter_score_flag (flag = pruned-src set), BEFORE pass-2 seg_init.
__global__ void k_markN() {
    int i = blockIdx.x * blockDim.x + threadIdx.x;
    if (i < N_NODES) {
        int sel = g_need0[i] && (g_flag[i] || !g_need1[i]);
        g_selN[i] = sel;
        if (sel) { int p = atomicAdd(&g_cntN, 1); g_cidN[i] = p; g_nlN[p] = i; }
    }
}

// per-query vectors from blocks of M = Wq^T Wk
__global__ void k_queryvec(const float* __restrict__ qst, const float* __restrict__ qr) {
    int q = blockIdx.x;
    int j = threadIdx.x;
    __shared__ float ss[256], tt[256], red[256];
    ss[j] = qst[q * D + j];
    tt[j] = qr[q * D + j];
    __syncthreads();
    int which = blockIdx.y;
    if (which == 0) {
        const float* row = g_M + (size_t)j * D4;
        float a = 0.f;
        for (int k = 0; k < D; k++) a += row[512 + k] * ss[k] + row[768 + k] * tt[k];
        g_v[q * D + j] = a;
    } else if (which == 1) {
        const float* row = g_M + (size_t)(256 + j) * D4;
        float a = 0.f;
        for (int k = 0; k < D; k++) a += row[512 + k] * ss[k] + row[768 + k] * tt[k];
        for (int k = 0; k < D; k++)
            a += g_M[(size_t)(512 + k) * D4 + 256 + j] * ss[k]
               + g_M[(size_t)(768 + k) * D4 + 256 + j] * tt[k];
        g_wz[q * D + j] = a;
    } else if (which == 2) {
        float a = 0.f;
        for (int k = 0; k < D; k++)
            a += g_M[(size_t)(512 + k) * D4 + j] * ss[k]
               + g_M[(size_t)(768 + k) * D4 + j] * tt[k];
        g_u[q * D + j] = a;
    } else {
        const float* rs = g_M + (size_t)(512 + j) * D4;
        const float* rt = g_M + (size_t)(768 + j) * D4;
        float ps = 0.f, pt = 0.f;
        for (int k = 0; k < D; k++) {
            ps += rs[512 + k] * ss[k] + rs[768 + k] * tt[k];
            pt += rt[512 + k] * ss[k] + rt[768 + k] * tt[k];
        }
        red[j] = ss[j] * ps + tt[j] * pt;
        __syncthreads();
        for (int s = 128; s; s >>= 1) {
            if (j < s) red[j] += red[j + s];
            __syncthreads();
        }
        if (j == 0) g_c[q] = red[0];
    }
}

// one warp per edge; each lane owns a contiguous 8-float span.
// pass 1: T at cid1. pass 0: per-edge select fresh (T1b/cidN) vs pass-1 (T1/cid1).
__global__ void k_edge_score(int pass, int nrid, const float* __restrict__ nrext,
                             const float* __restrict__ rel, int ne) {
    int e = blockIdx.x * 8 + (threadIdx.x >> 5);
    if (e >= ne) return;
    int lane = threadIdx.x & 31;
    const int* qs = pass ? g_q1 : g_q0;
    const int* ssrc = pass ? g_s1 : g_s0;
    const int* sdst = pass ? g_d1 : g_d0;
    const float* NR = nrid ? dbuf(nrid) : nrext;
    int q = qs[e], s = ssrc[e], d = sdst[e];
    int kb = lane * 8;
    const float *t1, *t2;
    if (pass) {
        int cd = g_cid1[d];
        t1 = g_T1 + (size_t)cd * D + kb;
        t2 = g_T2 + (size_t)cd * D + kb;
    } else if (g_selN[d]) {
        int cd = g_cidN[d];
        t1 = g_T1b + (size_t)cd * D + kb;
        t2 = g_T2b + (size_t)cd * D + kb;
    } else {
        int cd = g_cid1[d];
        t1 = g_T1 + (size_t)cd * D + kb;
        t2 = g_T2 + (size_t)cd * D + kb;
    }
    const float* ns = NR + (size_t)s * D + kb;
    const float* nd = NR + (size_t)d * D + kb;
    const float* re = rel + (size_t)e * D + kb;
    const float* r1 = g_R1 + (size_t)e * D + kb;
    const float* r2 = g_R2 + (size_t)e * D + kb;
    const float* vq = g_v + q * D + kb;
    const float* wq = g_wz + q * D + kb;
    const float* uq = g_u + q * D + kb;
    float a = 0.f;
#pragma unroll
    for (int h = 0; h < 8; h += 4) {
        float4 xn = *(const float4*)(ns + h);
        float4 xt1 = *(const float4*)(t1 + h);
        float4 xr1 = *(const float4*)(r1 + h);
        float4 xv = *(const float4*)(vq + h);
        a += xn.x * (xt1.x + xr1.x + xv.x) + xn.y * (xt1.y + xr1.y + xv.y)
           + xn.z * (xt1.z + xr1.z + xv.z) + xn.w * (xt1.w + xr1.w + xv.w);
        float4 xe = *(const float4*)(re + h);
        float4 xt2 = *(const float4*)(t2 + h);
        float4 xr2 = *(const float4*)(r2 + h);
        float4 xw = *(const float4*)(wq + h);
        a += xe.x * (xt2.x + xr2.x + xw.x) + xe.y * (xt2.y + xr2.y + xw.y)
           + xe.z * (xt2.z + xr2.z + xw.z) + xe.w * (xt2.w + xr2.w + xw.w);
        float4 xd = *(const float4*)(nd + h);
        float4 xu = *(const float4*)(uq + h);
        a += xd.x * xu.x + xd.y * xu.y + xd.z * xu.z + xd.w * xu.w;
    }
#pragma unroll
    for (int o = 16; o; o >>= 1) a += __shfl_xor_sync(0xffffffffu, a, o);
    if (lane == 0) g_logits[e] = a + g_c[q];
}

__global__ void k_seg_init() {
    int i = blockIdx.x * blockDim.x + threadIdx.x;
    if (i < N_NODES) {
        g_segmax[i] = 0u;
        g_segsum[i] = 0.f;
        g_flag[i] = 0;
    }
}

__global__ void k_seg_max(int pass, int ne) {
    int i = blockIdx.x * blockDim.x + threadIdx.x;
    if (i < ne) {
        const int* seg = pass ? g_s1 : g_s0;
        atomicMax(&g_segmax[seg[i]], fenc(g_logits[i]));
    }
}

__global__ void k_seg_exp(int pass, int ne) {
    int i = blockIdx.x * blockDim.x + threadIdx.x;
    if (i < ne) {
        const int* seg = pass ? g_s1 : g_s0;
        float m = fdec(g_segmax[seg[i]]);
        float e = expf(g_logits[i] - m);
        g_exp[i] = e;
        atomicAdd(&g_segsum[seg[i]], e);
    }
}

// per-query bitonic sort of 256 (target, idx); target computed inline
__global__ void k_topk(const int* __restrict__ edges1, int s32, int fm,
                       const float* __restrict__ vscore,
                       float* __restrict__ out_pe, float* __restrict__ out_oi) {
    int q = blockIdx.x;
    int t = threadIdx.x;
    __shared__ float sv[256];
    __shared__ int si[256];
    {
        int e = q * PG + t;
        int s = g_s1[e];
        float sft = g_exp[e] / g_segsum[s];
        sv[t] = sft * vscore[s];
    }
    si[t] = t;
    __syncthreads();
    for (int k = 2; k <= 256; k <<= 1) {
        for (int j = k >> 1; j > 0; j >>= 1) {
            int ixj = t ^ j;
            if (ixj > t) {
                float va = sv[t], vb = sv[ixj];
                int ia = si[t], ib = si[ixj];
                bool before = (va > vb) || (va == vb && ia < ib);
                bool up = ((t & k) == 0);
                if (up ? !before : before) {
                    sv[t] = vb; sv[ixj] = va;
                    si[t] = ib; si[ixj] = ia;
                }
            }
            __syncthreads();
        }
    }
    if (t < ME) {
        int oi = q * PG + si[t];
        int po = q * ME + t;
        out_oi[po] = (float)oi;
#pragma unroll
        for (int f = 0; f < 8; f++)
            out_pe[(size_t)po * 8 + f] = (float)edges1[(size_t)oi * s32 + f * fm];
        int s = edges1[(size_t)oi * s32 + 6 * fm];
        int d = edges1[(size_t)oi * s32 + 7 * fm];
        s = ((unsigned)s < N_NODES) ? s : 0;
        d = ((unsigned)d < N_NODES) ? d : 0;
        g_psrc[po] = s;
        g_pdst[po] = d;
        g_psoft[po] = g_exp[oi] / g_segsum[g_s1[oi]];
        g_ptgt[po] = sv[t];
    }
}

__global__ void k_zero_score(float* __restrict__ out_score) {
    int i = blockIdx.x * blockDim.x + threadIdx.x;
    if (i < N_NODES) out_score[i] = 0.f;
}

__global__ void k_scatter_score_flag(float* __restrict__ out_score) {
    int i = blockIdx.x * blockDim.x + threadIdx.x;
    if (i < NQ * ME) {
        atomicAdd(&out_score[g_pdst[i]], g_ptgt[i]);
        g_flag[g_psrc[i]] = 1;
    }
}

__global__ void k_set_flag0() {
    int i = blockIdx.x * blockDim.x + threadIdx.x;
    if (i < E0C) g_flag[g_s0[i]] = 1;
}

// mode 0: out = g_NR1, in = external NR ; mode 1: out = g_NR2, in = g_NR1
__global__ void k_scale_repr(int mode, const float* __restrict__ nrext) {
    size_t i = (size_t)blockIdx.x * blockDim.x + threadIdx.x;
    if (i < (size_t)N_NODES * (D / 4)) {
        const float4* in = mode ? (const float4*)g_NR1 : (const float4*)nrext;
        float4* out = mode ? (float4*)g_NR2 : (float4*)g_NR1;
        int n = (int)(i >> 6);
        float sc = g_flag[n] ? 0.2f : 1.0f;
        float4 vv = in[i];
        vv.x *= sc; vv.y *= sc; vv.z *= sc; vv.w *= sc;
        out[i] = vv;
    }
}

// mode 0: pruned edges (weight = g_psoft), base external NR, acc g_NR1
// mode 1: edges0 (weight = exp/segsum inline), base g_NR1, acc g_NR2
__global__ void k_edge_agg(int mode, const float* __restrict__ nrext, int ne) {
    int e = blockIdx.x * 8 + (threadIdx.x >> 5);
    if (e >= ne) return;
    int lane = threadIdx.x & 31;
    const int* src = mode ? g_s0 : g_psrc;
    const int* dst = mode ? g_d0 : g_pdst;
    const float* base = mode ? g_NR1 : nrext;
    float* acc = mode ? g_NR2 : g_NR1;
    float w;
    if (mode) w = g_exp[e] / g_segsum[src[e]];
    else w = g_psoft[e];
    float cf = 0.8f * w;
    const float* bd = base + (size_t)dst[e] * D;
    float* as = acc + (size_t)src[e] * D;
#pragma unroll
    for (int i = 0; i < 8; i++) atomicAdd(as + lane + 32 * i, cf * bd[lane + 32 * i]);
}

// ---------------- host: kernel launches ONLY ----------------
extern "C" void kernel_launch(void* const* d_in, const int* in_sizes, int n_in,
                              void* d_out, int out_size) {
    int iVS = -1, iNR = -1, iE0 = -1, iE1 = -1, iR0 = -1, iR1 = -1;
    int iQA = -1, iQB = -1, iWA = -1, iWB = -1, iWL = -1, iBL = -1;
    for (int i = 0; i < n_in; i++) {
        long sz = in_sizes[i];
        if (sz == 50000) iVS = i;
        else if (sz == 12800000) iNR = i;
        else if (sz == 262144 || sz == 524288) { if (iE0 < 0) iE0 = i; else iE1 = i; }
        else if (sz == 8388608) { if (iR0 < 0) iR0 = i; else iR1 = i; }
        else if (sz == 32768) { if (iQA < 0) iQA = i; else iQB = i; }
        else if (sz == 1048576) { if (iWA < 0) iWA = i; else iWB = i; }
        else if (sz == 65536) iWL = i;
        else if (sz == 256) iBL = i;
    }
    bool dictOrder = (in_sizes[0] == 50000);

    const float* vscore = (const float*)d_in[iVS];
    const float* NR = (const float*)d_in[iNR];
    const int* e0 = (const int*)d_in[iE0];
    const int* e1 = (const int*)d_in[iE1];
    const float* rel0 = (const float*)d_in[iR0];
    const float* rel1 = (const float*)d_in[iR1];
    const float* qst = (const float*)d_in[dictOrder ? iQA : iQB];
    const float* qr = (const float*)d_in[dictOrder ? iQB : iQA];
    const float* Wq = (const float*)d_in[dictOrder ? iWA : iWB];
    const float* Wk = (const float*)d_in[dictOrder ? iWB : iWA];
    const float* Wl = (const float*)d_in[iWL];
    const float* bl = (const float*)d_in[iBL];

    int s32 = in_sizes[iE0] / 32768;
    int fm = s32 >> 3;

    float* out = (float*)d_out;
    float* out_score = out;
    float* out_repr = out + N_NODES;
    float* out_pe = out_repr + (size_t)N_NODES * D;
    float* out_oi = out_pe + (size_t)NQ * ME * 8;

    const int NB50K = (N_NODES + 255) / 256;
    const int GRN = (N_NODES + 127) / 128;   // 391
    const int GRE = E1C / 128;               // 256

    k_extract<<<128, 256>>>(e1, e0, s32, fm);
    k_markinit<<<NB50K, 256>>>();
    k_mark<<<128, 256>>>();
    k_compact<<<NB50K, 256>>>();
    k_gemm128_tn<<<dim3(8, 8), 256>>>(Wq, Wk);
    k_splitw<<<512, 256>>>(nullptr, 1);
    k_splitw<<<512, 256>>>(nullptr, 2);
    k_splitw<<<256, 256>>>(Wl, 3);
    k_queryvec<<<dim3(NQ, 4), 256>>>(qst, qr);

    // ---- pass 1: T (compacted dst1 rows from NR) + R (rel1) in ONE launch ----
    k_gemm_dual<<<dim3(GRN + GRE, 4), 256>>>(
        NR, 0, N_NODES, 1, 1, BUF_T1, BUF_T2,
        rel1, 0, E1C, 2, 0, BUF_R1, BUF_R2,
        GRN, nullptr, 0, nullptr);

    // ---- pass 1 scores + segment softmax ----
    k_seg_init<<<NB50K, 256>>>();
    k_edge_score<<<E1C / 8, 256>>>(1, 0, NR, rel1, E1C);
    k_seg_max<<<128, 256>>>(1, E1C);
    k_seg_exp<<<128, 256>>>(1, E1C);

    // ---- top-64 per query (computes target + psoft inline) ----
    k_topk<<<NQ, 256>>>(e1, s32, fm, vscore, out_pe, out_oi);

    // ---- updated node score + repr update 1 ----
    k_zero_score<<<NB50K, 256>>>(out_score);
    k_scatter_score_flag<<<(NQ * ME + 255) / 256, 256>>>(out_score);
    k_markN<<<NB50K, 256>>>();   // needs flag (set above); before seg_init zeroes it
    k_scale_repr<<<(N_NODES * (D / 4) + 255) / 256, 256>>>(0, NR);
    k_edge_agg<<<NQ * ME / 8, 256>>>(0, NR, NQ * ME);

    // ---- pass 2: fresh T rows (dst0 ∩ (updated ∪ ¬dst1)) from NR1 + R (rel0), ONE launch ----
    k_gemm_dual<<<dim3(GRN + GRE, 4), 256>>>(
        nullptr, BUF_NR1, N_NODES, 1, 3, BUF_T1B, BUF_T2B,
        rel0, 0, E0C, 2, 0, BUF_R1, BUF_R2,
        GRN, nullptr, 0, nullptr);

    // ---- pass 2 scores + softmax ----
    k_seg_init<<<NB50K, 256>>>();
    k_edge_score<<<E0C / 8, 256>>>(0, BUF_NR1, nullptr, rel0, E0C);
    k_seg_max<<<128, 256>>>(0, E0C);
    k_seg_exp<<<128, 256>>>(0, E0C);

    // ---- repr update 2 ----
    k_set_flag0<<<128, 256>>>();
    k_scale_repr<<<(N_NODES * (D / 4) + 255) / 256, 256>>>(1, nullptr);
    k_edge_agg<<<E0C / 8, 256>>>(1, nullptr, E0C);

    // ---- final linear layer + leaky relu (N=256 external out, full node set) ----
    k_gemm_dual<<<dim3(GRN, 2), 256>>>(
        nullptr, BUF_NR2, N_NODES, 3, 0, 0, 0,
        nullptr, BUF_NR2, N_NODES, 3, 0, 0, 0,
        GRN, bl, 1, out_repr);
}